// round 16
// baseline (speedup 1.0000x reference)
#include <cuda_runtime.h>
#include <cuda_fp16.h>
#include <cstdint>

#define N_NODES 40000
#define N_EDGES 640000
#define D 128
#define TILE_M 64
#define NTILES 626                     // 40064 / 64
#define PADROWS (NTILES * TILE_M)      // 40064
#define PGRID 444                      // persistent gemm grid: 3 CTAs/SM x 148
#define AGRID 1184                     // persistent agg grid: 8 CTAs/SM x 148
#define SLOT_CAP 64                    // max degree capacity (Poisson(16): P(>64)~1e-20)

// ---------------------------------------------------------------------------
// Device scratch (zero-initialized at module load; pad rows stay 0 forever).
// g_deg re-zeroed by the LAST kernel of each launch (replay-safe, proven R7+).
// ---------------------------------------------------------------------------
__device__ int   g_deg[N_NODES];
__device__ int   g_slots[(size_t)N_NODES * SLOT_CAP];   // src ids per dst node
// fp16 operand images, row-major [PADROWS][128]
__device__ unsigned short g_Ah[(size_t)PADROWS * D];    // self feats (agg gather source)
__device__ unsigned short g_Aa[(size_t)PADROWS * D];    // aggregated feats
// weight image (fp16): [layer][n=128][kv=256] (kv<128: Ws^T, else Wn^T)
__device__ unsigned short g_Bimg[3][128][256];

// ---------------------------------------------------------------------------
// Helpers
// ---------------------------------------------------------------------------
__device__ __forceinline__ void store_hi4(unsigned short* hi, size_t idx, float4 v) {
    half2 p0 = __floats2half2_rn(v.x, v.y);
    half2 p1 = __floats2half2_rn(v.z, v.w);
    *(uint2*)(hi + idx) = make_uint2(*(uint32_t*)&p0, *(uint32_t*)&p1);
}

__device__ __forceinline__ void mma16816(float* c, const uint32_t* a, const uint32_t* b) {
    asm volatile(
        "mma.sync.aligned.m16n8k16.row.col.f32.f16.f16.f32 "
        "{%0,%1,%2,%3}, {%4,%5,%6,%7}, {%8,%9}, {%0,%1,%2,%3};"
        : "+f"(c[0]), "+f"(c[1]), "+f"(c[2]), "+f"(c[3])
        : "r"(a[0]), "r"(a[1]), "r"(a[2]), "r"(a[3]), "r"(b[0]), "r"(b[1]));
}

__device__ __forceinline__ uint32_t smem_u32(const void* p) {
    uint32_t a;
    asm("{ .reg .u64 t; cvta.to.shared.u64 t, %1; cvt.u32.u64 %0, t; }" : "=r"(a) : "l"(p));
    return a;
}

__device__ __forceinline__ void cp16(uint32_t s, const void* g) {
    asm volatile("cp.async.cg.shared.global [%0], [%1], 16;" :: "r"(s), "l"(g));
}
#define CP_COMMIT() asm volatile("cp.async.commit_group;" ::: "memory")
#define CP_WAIT(n)  asm volatile("cp.async.wait_group %0;" :: "n"(n) : "memory")

// ---------------------------------------------------------------------------
// Prep (fully merged): weight image + x->fp16 self image + slot-table fill.
// ---------------------------------------------------------------------------
__global__ void __launch_bounds__(256) prep_kernel(
    const float* __restrict__ x, const float* __restrict__ ws,
    const float* __restrict__ wn,
    const int* __restrict__ src, const int* __restrict__ dst)
{
    int tid = blockIdx.x * 256 + threadIdx.x;      // 0..1279999
    if (tid < 3 * 128 * 256) {                     // weight image (fp16)
        int l = tid >> 15;
        int rem = tid & 32767;
        int n = rem >> 8;
        int kv = rem & 255;
        float v = (kv < 128) ? ws[l * 16384 + kv * 128 + n]
                             : wn[l * 16384 + (kv - 128) * 128 + n];
        g_Bimg[l][n][kv] = __half_as_ushort(__float2half_rn(v));
    }
    if (tid < N_EDGES) {                           // direct edge -> slot fill
        int d = dst[tid];
        int slot = atomicAdd(&g_deg[d], 1) & (SLOT_CAP - 1);
        g_slots[(size_t)d * SLOT_CAP + slot] = src[tid];
    }
    int node = tid >> 5;                           // x -> fp16 self image
    int lane = tid & 31;
    if (node < N_NODES) {
        float4 v = ((const float4*)x)[node * 32 + lane];
        store_hi4(g_Ah, (size_t)node * D + lane * 4, v);
    }
}

// ---------------------------------------------------------------------------
// Aggregation: PERSISTENT grid (8 CTAs/SM), one warp per node per step.
// 8-wide gather groups: both int4 slot loads + all 8 row-gathers issued
// before any arithmetic (MLP=8); two independent fp16 trees-of-4 flushed to
// fp32 (numerically identical to the per-4 scheme).
// ---------------------------------------------------------------------------
__global__ void __launch_bounds__(256, 8) agg_kernel() {
    int warp0 = (blockIdx.x * blockDim.x + threadIdx.x) >> 5;
    int lane = threadIdx.x & 31;
    const uint2* __restrict__ h2 = (const uint2*)g_Ah;

    for (int node = warp0; node < N_NODES; node += AGRID * 8) {
        int deg = g_deg[node];
        const int4* __restrict__ sl4 = (const int4*)(g_slots + (size_t)node * SLOT_CAP);

        float4 acc = make_float4(0.f, 0.f, 0.f, 0.f);
        int i = 0;
        for (; i + 8 <= deg; i += 8) {
            int4 sa = sl4[(i >> 2)];
            int4 sb = sl4[(i >> 2) + 1];
            // issue all 8 gathers before any math
            uint2 u0 = h2[sa.x * 32 + lane];
            uint2 u1 = h2[sa.y * 32 + lane];
            uint2 u2 = h2[sa.z * 32 + lane];
            uint2 u3 = h2[sa.w * 32 + lane];
            uint2 v0 = h2[sb.x * 32 + lane];
            uint2 v1 = h2[sb.y * 32 + lane];
            uint2 v2 = h2[sb.z * 32 + lane];
            uint2 v3 = h2[sb.w * 32 + lane];
            half2 xs0 = __hadd2(__hadd2(*(half2*)&u0.x, *(half2*)&u1.x),
                                __hadd2(*(half2*)&u2.x, *(half2*)&u3.x));
            half2 ys0 = __hadd2(__hadd2(*(half2*)&u0.y, *(half2*)&u1.y),
                                __hadd2(*(half2*)&u2.y, *(half2*)&u3.y));
            half2 xs1 = __hadd2(__hadd2(*(half2*)&v0.x, *(half2*)&v1.x),
                                __hadd2(*(half2*)&v2.x, *(half2*)&v3.x));
            half2 ys1 = __hadd2(__hadd2(*(half2*)&v0.y, *(half2*)&v1.y),
                                __hadd2(*(half2*)&v2.y, *(half2*)&v3.y));
            float2 fx0 = __half22float2(xs0), fy0 = __half22float2(ys0);
            float2 fx1 = __half22float2(xs1), fy1 = __half22float2(ys1);
            acc.x += fx0.x + fx1.x; acc.y += fx0.y + fx1.y;
            acc.z += fy0.x + fy1.x; acc.w += fy0.y + fy1.y;
        }
        if (i + 4 <= deg) {
            int4 s = sl4[i >> 2];
            uint2 u0 = h2[s.x * 32 + lane];
            uint2 u1 = h2[s.y * 32 + lane];
            uint2 u2 = h2[s.z * 32 + lane];
            uint2 u3 = h2[s.w * 32 + lane];
            half2 xs = __hadd2(__hadd2(*(half2*)&u0.x, *(half2*)&u1.x),
                               __hadd2(*(half2*)&u2.x, *(half2*)&u3.x));
            half2 ys = __hadd2(__hadd2(*(half2*)&u0.y, *(half2*)&u1.y),
                               __hadd2(*(half2*)&u2.y, *(half2*)&u3.y));
            float2 fx = __half22float2(xs), fy = __half22float2(ys);
            acc.x += fx.x; acc.y += fx.y; acc.z += fy.x; acc.w += fy.y;
            i += 4;
        }
        if (i < deg) {
            int4 s = sl4[i >> 2];
            const int sv[4] = {s.x, s.y, s.z, s.w};
            int rem = deg - i;
            for (int j = 0; j < rem; j++) {
                uint2 u0 = h2[sv[j] * 32 + lane];
                float2 a0 = __half22float2(*(half2*)&u0.x);
                float2 b0 = __half22float2(*(half2*)&u0.y);
                acc.x += a0.x; acc.y += a0.y; acc.z += b0.x; acc.w += b0.y;
            }
        }
        float inv = (deg > 0) ? 1.0f / (float)deg : 1.0f;
        acc.x *= inv; acc.y *= inv; acc.z *= inv; acc.w *= inv;
        store_hi4(g_Aa, (size_t)node * D + lane * 4, acc);
    }
}

// ---------------------------------------------------------------------------
// PERSISTENT single-pass fp16 mma.sync GEMM (unchanged from R15).
// Grid = 444 CTAs (3/SM), tile-strided. A SMEM-resident; B double-buffered
// in four 64-wide k-chunks. smem ~72KB -> 3 CTAs/SM.
// ---------------------------------------------------------------------------
#define RPA 68                          // A row stride (words)
#define RPB 36                          // B row stride (words)
#define A_IMG (64 * RPA)                // 4352 words
#define OFF_AS 0
#define OFF_AA A_IMG
#define B_IMG (128 * RPB)               // 4608 words per chunk buffer
#define OFF_B  (2 * A_IMG)              // 8704
#define OFF_BIAS (2 * A_IMG + 2 * B_IMG)  // 17920
#define SMEM_WORDS (OFF_BIAS + 128)     // 18048 words = 72192 B

__global__ void __launch_bounds__(256, 3) mma_gemm_kernel(
    int layer, const float* __restrict__ bias, float* __restrict__ out,
    int do_relu, int write_img, int cleanup)
{
    extern __shared__ __align__(16) uint32_t sm[];
    uint32_t smb = smem_u32(sm);

    int tid = threadIdx.x;
    int wid = tid >> 5, lane = tid & 31;
    int wm = wid >> 2;
    int wn = wid & 3;
    int g = lane >> 2;
    int c = lane & 3;

    if (cleanup) {            // zero deg for the NEXT launch (replay-safe)
        for (int gid = blockIdx.x * 256 + tid; gid < N_NODES; gid += PGRID * 256)
            g_deg[gid] = 0;
    }
    if (tid < 128) sm[OFF_BIAS + tid] = __float_as_uint(bias[tid]);
    __syncthreads();
    const float* bias_sm = (const float*)(sm + OFF_BIAS);

    for (int tile = blockIdx.x; tile < NTILES; tile += PGRID) {
        size_t row0 = (size_t)tile * TILE_M;

        float acc[2][4][4];
        #pragma unroll
        for (int mf = 0; mf < 2; mf++)
            #pragma unroll
            for (int nf = 0; nf < 4; nf++)
                #pragma unroll
                for (int k = 0; k < 4; k++) acc[mf][nf][k] = 0.f;

        // --- stage all of A (2 images x 64 rows x 16 segs of 16B) ---
        {
            #pragma unroll
            for (int it = 0; it < 8; it++) {
                int i = tid + it * 256;       // 0..2047
                int img = i >> 10;
                int rem = i & 1023;
                int r = rem >> 4;
                int seg = rem & 15;
                const unsigned short* srcp = (img ? g_Aa : g_Ah) + (row0 + r) * D + seg * 8;
                cp16(smb + ((img ? OFF_AA : OFF_AS) + r * RPA + seg * 4) * 4, srcp);
            }
        }
        // --- stage one 64-wide B chunk (128 n x 64 kv = 8 segs/row) ---
        auto stageB = [&](int ch, int buf) {
            #pragma unroll
            for (int it = 0; it < 4; it++) {
                int i = tid + it * 256;       // 0..1023
                int n = i >> 3;
                int seg = i & 7;
                cp16(smb + (OFF_B + buf * B_IMG + n * RPB + seg * 4) * 4,
                     &g_Bimg[layer][n][ch * 64 + seg * 8]);
            }
        };

        stageB(0, 0);
        CP_COMMIT();

        for (int ch = 0; ch < 4; ch++) {
            int buf = ch & 1;
            if (ch < 3) {
                stageB(ch + 1, buf ^ 1);
                CP_COMMIT();
                CP_WAIT(1);
            } else {
                CP_WAIT(0);
            }
            __syncthreads();

            const uint32_t* Aimg = sm + ((ch < 2) ? OFF_AS : OFF_AA);
            const uint32_t* B0 = sm + OFF_B + buf * B_IMG;
            int chm = (ch & 1) * 32;          // A word base within row

            #pragma unroll
            for (int kk = 0; kk < 4; kk++) {
                uint32_t ah[2][4], bh[4][2];
                #pragma unroll
                for (int mf = 0; mf < 2; mf++) {
                    int wb = (wm * 32 + mf * 16 + g) * RPA + chm + kk * 8 + c;
                    ah[mf][0] = Aimg[wb];
                    ah[mf][1] = Aimg[wb + 8 * RPA];
                    ah[mf][2] = Aimg[wb + 4];
                    ah[mf][3] = Aimg[wb + 8 * RPA + 4];
                }
                #pragma unroll
                for (int nf = 0; nf < 4; nf++) {
                    int wb = (wn * 32 + nf * 8 + g) * RPB + kk * 8 + c;
                    bh[nf][0] = B0[wb];
                    bh[nf][1] = B0[wb + 4];
                }
                #pragma unroll
                for (int mf = 0; mf < 2; mf++)
                    #pragma unroll
                    for (int nf = 0; nf < 4; nf++)
                        mma16816(acc[mf][nf], ah[mf], bh[nf]);
            }
            __syncthreads();
        }

        // --- epilogue: bias + relu; write fp16 image (layers 0,1) or fp32 ---
        #pragma unroll
        for (int mf = 0; mf < 2; mf++) {
            size_t r_lo = row0 + wm * 32 + mf * 16 + g;
            size_t r_hi = r_lo + 8;
            #pragma unroll
            for (int nf = 0; nf < 4; nf++) {
                int col = wn * 32 + nf * 8 + c * 2;
                float b0 = bias_sm[col], b1 = bias_sm[col + 1];
                float v00 = acc[mf][nf][0] + b0, v01 = acc[mf][nf][1] + b1;
                float v10 = acc[mf][nf][2] + b0, v11 = acc[mf][nf][3] + b1;
                if (do_relu) {
                    v00 = fmaxf(v00, 0.f); v01 = fmaxf(v01, 0.f);
                    v10 = fmaxf(v10, 0.f); v11 = fmaxf(v11, 0.f);
                }
                if (r_lo < N_NODES) {
                    if (write_img) {
                        half2 p = __floats2half2_rn(v00, v01);
                        *(uint32_t*)(g_Ah + r_lo * D + col) = *(uint32_t*)&p;
                    } else {
                        *(float2*)(out + r_lo * D + col) = make_float2(v00, v01);
                    }
                }
                if (r_hi < N_NODES) {
                    if (write_img) {
                        half2 p = __floats2half2_rn(v10, v11);
                        *(uint32_t*)(g_Ah + r_hi * D + col) = *(uint32_t*)&p;
                    } else {
                        *(float2*)(out + r_hi * D + col) = make_float2(v10, v11);
                    }
                }
            }
        }
    }
}

// ---------------------------------------------------------------------------
// Launch
// ---------------------------------------------------------------------------
extern "C" void kernel_launch(void* const* d_in, const int* in_sizes, int n_in,
                              void* d_out, int out_size) {
    const float* x       = (const float*)d_in[0];
    const int*   src     = (const int*)d_in[1];
    const int*   dst     = (const int*)d_in[2];
    const float* w_self  = (const float*)d_in[3];
    const float* w_neigh = (const float*)d_in[4];
    const float* b       = (const float*)d_in[5];
    float*       out     = (float*)d_out;

    cudaFuncSetAttribute(mma_gemm_kernel, cudaFuncAttributeMaxDynamicSharedMemorySize,
                         SMEM_WORDS * 4);

    // Single prep launch: weights + x image + slot-table edge fill
    prep_kernel<<<5000, 256>>>(x, w_self, w_neigh, src, dst);

    // Layer 0
    agg_kernel<<<AGRID, 256>>>();
    mma_gemm_kernel<<<PGRID, 256, SMEM_WORDS * 4>>>(0, b, nullptr, 1, 1, 0);
    // Layer 1
    agg_kernel<<<AGRID, 256>>>();
    mma_gemm_kernel<<<PGRID, 256, SMEM_WORDS * 4>>>(1, b + 128, nullptr, 1, 1, 0);
    // Layer 2: fp32 -> out (no relu); cleanup zeroes deg for next call
    agg_kernel<<<AGRID, 256>>>();
    mma_gemm_kernel<<<PGRID, 256, SMEM_WORDS * 4>>>(2, b + 256, out, 0, 0, 1);
}

// round 17
// speedup vs baseline: 1.0504x; 1.0504x over previous
#include <cuda_runtime.h>
#include <cuda_fp16.h>
#include <cstdint>

#define N_NODES 40000
#define N_EDGES 640000
#define D 128
#define TILE_M 64
#define NTILES 626                     // 40064 / 64
#define PADROWS (NTILES * TILE_M)      // 40064
#define PGRID 444                      // persistent gemm grid: 3 CTAs/SM x 148
#define AGRID 888                      // persistent agg grid: 6 CTAs/SM x 148
#define SLOT_CAP 64                    // max degree capacity (Poisson(16): P(>64)~1e-20)

// ---------------------------------------------------------------------------
// Device scratch (zero-initialized at module load; pad rows stay 0 forever).
// g_deg re-zeroed by the LAST kernel of each launch (replay-safe, proven R7+).
// ---------------------------------------------------------------------------
__device__ int   g_deg[N_NODES];
__device__ int   g_slots[(size_t)N_NODES * SLOT_CAP];   // src ids per dst node
// fp16 operand images, row-major [PADROWS][128]
__device__ unsigned short g_Ah[(size_t)PADROWS * D];    // self feats (agg gather source)
__device__ unsigned short g_Aa[(size_t)PADROWS * D];    // aggregated feats
// weight image (fp16): [layer][n=128][kv=256] (kv<128: Ws^T, else Wn^T)
__device__ unsigned short g_Bimg[3][128][256];

// ---------------------------------------------------------------------------
// Helpers
// ---------------------------------------------------------------------------
__device__ __forceinline__ void store_hi4(unsigned short* hi, size_t idx, float4 v) {
    half2 p0 = __floats2half2_rn(v.x, v.y);
    half2 p1 = __floats2half2_rn(v.z, v.w);
    *(uint2*)(hi + idx) = make_uint2(*(uint32_t*)&p0, *(uint32_t*)&p1);
}

__device__ __forceinline__ void mma16816(float* c, const uint32_t* a, const uint32_t* b) {
    asm volatile(
        "mma.sync.aligned.m16n8k16.row.col.f32.f16.f16.f32 "
        "{%0,%1,%2,%3}, {%4,%5,%6,%7}, {%8,%9}, {%0,%1,%2,%3};"
        : "+f"(c[0]), "+f"(c[1]), "+f"(c[2]), "+f"(c[3])
        : "r"(a[0]), "r"(a[1]), "r"(a[2]), "r"(a[3]), "r"(b[0]), "r"(b[1]));
}

__device__ __forceinline__ uint32_t smem_u32(const void* p) {
    uint32_t a;
    asm("{ .reg .u64 t; cvta.to.shared.u64 t, %1; cvt.u32.u64 %0, t; }" : "=r"(a) : "l"(p));
    return a;
}

__device__ __forceinline__ void cp16(uint32_t s, const void* g) {
    asm volatile("cp.async.cg.shared.global [%0], [%1], 16;" :: "r"(s), "l"(g));
}
#define CP_COMMIT() asm volatile("cp.async.commit_group;" ::: "memory")
#define CP_WAIT(n)  asm volatile("cp.async.wait_group %0;" :: "n"(n) : "memory")

// ---------------------------------------------------------------------------
// Prep (fully merged): weight image + x->fp16 self image + slot-table fill.
// ---------------------------------------------------------------------------
__global__ void __launch_bounds__(256) prep_kernel(
    const float* __restrict__ x, const float* __restrict__ ws,
    const float* __restrict__ wn,
    const int* __restrict__ src, const int* __restrict__ dst)
{
    int tid = blockIdx.x * 256 + threadIdx.x;      // 0..1279999
    if (tid < 3 * 128 * 256) {                     // weight image (fp16)
        int l = tid >> 15;
        int rem = tid & 32767;
        int n = rem >> 8;
        int kv = rem & 255;
        float v = (kv < 128) ? ws[l * 16384 + kv * 128 + n]
                             : wn[l * 16384 + (kv - 128) * 128 + n];
        g_Bimg[l][n][kv] = __half_as_ushort(__float2half_rn(v));
    }
    if (tid < N_EDGES) {                           // direct edge -> slot fill
        int d = dst[tid];
        int slot = atomicAdd(&g_deg[d], 1) & (SLOT_CAP - 1);
        g_slots[(size_t)d * SLOT_CAP + slot] = src[tid];
    }
    int node = tid >> 5;                           // x -> fp16 self image
    int lane = tid & 31;
    if (node < N_NODES) {
        float4 v = ((const float4*)x)[node * 32 + lane];
        store_hi4(g_Ah, (size_t)node * D + lane * 4, v);
    }
}

// ---------------------------------------------------------------------------
// Aggregation: PERSISTENT grid, one warp per node per step.
// Lane-distributed slot ids: ONE coalesced load of sl[lane] covers deg<=32
// (always, Poisson(16)); neighbor ids then come from __shfl_sync, so all
// row-gathers for the node are independent (MLP ~= deg). deg>32 tail (~1e-4
// of nodes) reads sl[i] directly. Arithmetic trees identical to R15/R16.
// ---------------------------------------------------------------------------
__global__ void __launch_bounds__(256, 6) agg_kernel() {
    int warp0 = (blockIdx.x * blockDim.x + threadIdx.x) >> 5;
    int lane = threadIdx.x & 31;
    const uint2* __restrict__ h2 = (const uint2*)g_Ah;

    for (int node = warp0; node < N_NODES; node += AGRID * 8) {
        int deg = g_deg[node];
        const int* __restrict__ sl = g_slots + (size_t)node * SLOT_CAP;
        int sid = sl[lane];                       // coalesced; used only for idx<deg
        int deg32 = deg < 32 ? deg : 32;

        float4 acc = make_float4(0.f, 0.f, 0.f, 0.f);
        int i = 0;
        for (; i + 8 <= deg32; i += 8) {
            int s0 = __shfl_sync(0xffffffffu, sid, i + 0);
            int s1 = __shfl_sync(0xffffffffu, sid, i + 1);
            int s2 = __shfl_sync(0xffffffffu, sid, i + 2);
            int s3 = __shfl_sync(0xffffffffu, sid, i + 3);
            int s4 = __shfl_sync(0xffffffffu, sid, i + 4);
            int s5 = __shfl_sync(0xffffffffu, sid, i + 5);
            int s6 = __shfl_sync(0xffffffffu, sid, i + 6);
            int s7 = __shfl_sync(0xffffffffu, sid, i + 7);
            uint2 u0 = h2[s0 * 32 + lane];
            uint2 u1 = h2[s1 * 32 + lane];
            uint2 u2 = h2[s2 * 32 + lane];
            uint2 u3 = h2[s3 * 32 + lane];
            uint2 v0 = h2[s4 * 32 + lane];
            uint2 v1 = h2[s5 * 32 + lane];
            uint2 v2 = h2[s6 * 32 + lane];
            uint2 v3 = h2[s7 * 32 + lane];
            half2 xs0 = __hadd2(__hadd2(*(half2*)&u0.x, *(half2*)&u1.x),
                                __hadd2(*(half2*)&u2.x, *(half2*)&u3.x));
            half2 ys0 = __hadd2(__hadd2(*(half2*)&u0.y, *(half2*)&u1.y),
                                __hadd2(*(half2*)&u2.y, *(half2*)&u3.y));
            half2 xs1 = __hadd2(__hadd2(*(half2*)&v0.x, *(half2*)&v1.x),
                                __hadd2(*(half2*)&v2.x, *(half2*)&v3.x));
            half2 ys1 = __hadd2(__hadd2(*(half2*)&v0.y, *(half2*)&v1.y),
                                __hadd2(*(half2*)&v2.y, *(half2*)&v3.y));
            float2 fx0 = __half22float2(xs0), fy0 = __half22float2(ys0);
            float2 fx1 = __half22float2(xs1), fy1 = __half22float2(ys1);
            acc.x += fx0.x + fx1.x; acc.y += fx0.y + fx1.y;
            acc.z += fy0.x + fy1.x; acc.w += fy0.y + fy1.y;
        }
        if (i + 4 <= deg32) {
            int s0 = __shfl_sync(0xffffffffu, sid, i + 0);
            int s1 = __shfl_sync(0xffffffffu, sid, i + 1);
            int s2 = __shfl_sync(0xffffffffu, sid, i + 2);
            int s3 = __shfl_sync(0xffffffffu, sid, i + 3);
            uint2 u0 = h2[s0 * 32 + lane];
            uint2 u1 = h2[s1 * 32 + lane];
            uint2 u2 = h2[s2 * 32 + lane];
            uint2 u3 = h2[s3 * 32 + lane];
            half2 xs = __hadd2(__hadd2(*(half2*)&u0.x, *(half2*)&u1.x),
                               __hadd2(*(half2*)&u2.x, *(half2*)&u3.x));
            half2 ys = __hadd2(__hadd2(*(half2*)&u0.y, *(half2*)&u1.y),
                               __hadd2(*(half2*)&u2.y, *(half2*)&u3.y));
            float2 fx = __half22float2(xs), fy = __half22float2(ys);
            acc.x += fx.x; acc.y += fx.y; acc.z += fy.x; acc.w += fy.y;
            i += 4;
        }
        for (; i < deg32; i++) {
            int s0 = __shfl_sync(0xffffffffu, sid, i);
            uint2 u0 = h2[s0 * 32 + lane];
            float2 a0 = __half22float2(*(half2*)&u0.x);
            float2 b0 = __half22float2(*(half2*)&u0.y);
            acc.x += a0.x; acc.y += a0.y; acc.z += b0.x; acc.w += b0.y;
        }
        for (int j = 32; j < deg; j++) {          // rare deg>32 tail
            uint2 u0 = h2[sl[j] * 32 + lane];
            float2 a0 = __half22float2(*(half2*)&u0.x);
            float2 b0 = __half22float2(*(half2*)&u0.y);
            acc.x += a0.x; acc.y += a0.y; acc.z += b0.x; acc.w += b0.y;
        }
        float inv = (deg > 0) ? 1.0f / (float)deg : 1.0f;
        acc.x *= inv; acc.y *= inv; acc.z *= inv; acc.w *= inv;
        store_hi4(g_Aa, (size_t)node * D + lane * 4, acc);
    }
}

// ---------------------------------------------------------------------------
// PERSISTENT single-pass fp16 mma.sync GEMM (unchanged from R15).
// Grid = 444 CTAs (3/SM), tile-strided. A SMEM-resident; B double-buffered
// in four 64-wide k-chunks. smem ~72KB -> 3 CTAs/SM.
// ---------------------------------------------------------------------------
#define RPA 68                          // A row stride (words)
#define RPB 36                          // B row stride (words)
#define A_IMG (64 * RPA)                // 4352 words
#define OFF_AS 0
#define OFF_AA A_IMG
#define B_IMG (128 * RPB)               // 4608 words per chunk buffer
#define OFF_B  (2 * A_IMG)              // 8704
#define OFF_BIAS (2 * A_IMG + 2 * B_IMG)  // 17920
#define SMEM_WORDS (OFF_BIAS + 128)     // 18048 words = 72192 B

__global__ void __launch_bounds__(256, 3) mma_gemm_kernel(
    int layer, const float* __restrict__ bias, float* __restrict__ out,
    int do_relu, int write_img, int cleanup)
{
    extern __shared__ __align__(16) uint32_t sm[];
    uint32_t smb = smem_u32(sm);

    int tid = threadIdx.x;
    int wid = tid >> 5, lane = tid & 31;
    int wm = wid >> 2;
    int wn = wid & 3;
    int g = lane >> 2;
    int c = lane & 3;

    if (cleanup) {            // zero deg for the NEXT launch (replay-safe)
        for (int gid = blockIdx.x * 256 + tid; gid < N_NODES; gid += PGRID * 256)
            g_deg[gid] = 0;
    }
    if (tid < 128) sm[OFF_BIAS + tid] = __float_as_uint(bias[tid]);
    __syncthreads();
    const float* bias_sm = (const float*)(sm + OFF_BIAS);

    for (int tile = blockIdx.x; tile < NTILES; tile += PGRID) {
        size_t row0 = (size_t)tile * TILE_M;

        float acc[2][4][4];
        #pragma unroll
        for (int mf = 0; mf < 2; mf++)
            #pragma unroll
            for (int nf = 0; nf < 4; nf++)
                #pragma unroll
                for (int k = 0; k < 4; k++) acc[mf][nf][k] = 0.f;

        // --- stage all of A (2 images x 64 rows x 16 segs of 16B) ---
        {
            #pragma unroll
            for (int it = 0; it < 8; it++) {
                int i = tid + it * 256;       // 0..2047
                int img = i >> 10;
                int rem = i & 1023;
                int r = rem >> 4;
                int seg = rem & 15;
                const unsigned short* srcp = (img ? g_Aa : g_Ah) + (row0 + r) * D + seg * 8;
                cp16(smb + ((img ? OFF_AA : OFF_AS) + r * RPA + seg * 4) * 4, srcp);
            }
        }
        // --- stage one 64-wide B chunk (128 n x 64 kv = 8 segs/row) ---
        auto stageB = [&](int ch, int buf) {
            #pragma unroll
            for (int it = 0; it < 4; it++) {
                int i = tid + it * 256;       // 0..1023
                int n = i >> 3;
                int seg = i & 7;
                cp16(smb + (OFF_B + buf * B_IMG + n * RPB + seg * 4) * 4,
                     &g_Bimg[layer][n][ch * 64 + seg * 8]);
            }
        };

        stageB(0, 0);
        CP_COMMIT();

        for (int ch = 0; ch < 4; ch++) {
            int buf = ch & 1;
            if (ch < 3) {
                stageB(ch + 1, buf ^ 1);
                CP_COMMIT();
                CP_WAIT(1);
            } else {
                CP_WAIT(0);
            }
            __syncthreads();

            const uint32_t* Aimg = sm + ((ch < 2) ? OFF_AS : OFF_AA);
            const uint32_t* B0 = sm + OFF_B + buf * B_IMG;
            int chm = (ch & 1) * 32;          // A word base within row

            #pragma unroll
            for (int kk = 0; kk < 4; kk++) {
                uint32_t ah[2][4], bh[4][2];
                #pragma unroll
                for (int mf = 0; mf < 2; mf++) {
                    int wb = (wm * 32 + mf * 16 + g) * RPA + chm + kk * 8 + c;
                    ah[mf][0] = Aimg[wb];
                    ah[mf][1] = Aimg[wb + 8 * RPA];
                    ah[mf][2] = Aimg[wb + 4];
                    ah[mf][3] = Aimg[wb + 8 * RPA + 4];
                }
                #pragma unroll
                for (int nf = 0; nf < 4; nf++) {
                    int wb = (wn * 32 + nf * 8 + g) * RPB + kk * 8 + c;
                    bh[nf][0] = B0[wb];
                    bh[nf][1] = B0[wb + 4];
                }
                #pragma unroll
                for (int mf = 0; mf < 2; mf++)
                    #pragma unroll
                    for (int nf = 0; nf < 4; nf++)
                        mma16816(acc[mf][nf], ah[mf], bh[nf]);
            }
            __syncthreads();
        }

        // --- epilogue: bias + relu; write fp16 image (layers 0,1) or fp32 ---
        #pragma unroll
        for (int mf = 0; mf < 2; mf++) {
            size_t r_lo = row0 + wm * 32 + mf * 16 + g;
            size_t r_hi = r_lo + 8;
            #pragma unroll
            for (int nf = 0; nf < 4; nf++) {
                int col = wn * 32 + nf * 8 + c * 2;
                float b0 = bias_sm[col], b1 = bias_sm[col + 1];
                float v00 = acc[mf][nf][0] + b0, v01 = acc[mf][nf][1] + b1;
                float v10 = acc[mf][nf][2] + b0, v11 = acc[mf][nf][3] + b1;
                if (do_relu) {
                    v00 = fmaxf(v00, 0.f); v01 = fmaxf(v01, 0.f);
                    v10 = fmaxf(v10, 0.f); v11 = fmaxf(v11, 0.f);
                }
                if (r_lo < N_NODES) {
                    if (write_img) {
                        half2 p = __floats2half2_rn(v00, v01);
                        *(uint32_t*)(g_Ah + r_lo * D + col) = *(uint32_t*)&p;
                    } else {
                        *(float2*)(out + r_lo * D + col) = make_float2(v00, v01);
                    }
                }
                if (r_hi < N_NODES) {
                    if (write_img) {
                        half2 p = __floats2half2_rn(v10, v11);
                        *(uint32_t*)(g_Ah + r_hi * D + col) = *(uint32_t*)&p;
                    } else {
                        *(float2*)(out + r_hi * D + col) = make_float2(v10, v11);
                    }
                }
            }
        }
    }
}

// ---------------------------------------------------------------------------
// Launch
// ---------------------------------------------------------------------------
extern "C" void kernel_launch(void* const* d_in, const int* in_sizes, int n_in,
                              void* d_out, int out_size) {
    const float* x       = (const float*)d_in[0];
    const int*   src     = (const int*)d_in[1];
    const int*   dst     = (const int*)d_in[2];
    const float* w_self  = (const float*)d_in[3];
    const float* w_neigh = (const float*)d_in[4];
    const float* b       = (const float*)d_in[5];
    float*       out     = (float*)d_out;

    cudaFuncSetAttribute(mma_gemm_kernel, cudaFuncAttributeMaxDynamicSharedMemorySize,
                         SMEM_WORDS * 4);

    // Single prep launch: weights + x image + slot-table edge fill
    prep_kernel<<<5000, 256>>>(x, w_self, w_neigh, src, dst);

    // Layer 0
    agg_kernel<<<AGRID, 256>>>();
    mma_gemm_kernel<<<PGRID, 256, SMEM_WORDS * 4>>>(0, b, nullptr, 1, 1, 0);
    // Layer 1
    agg_kernel<<<AGRID, 256>>>();
    mma_gemm_kernel<<<PGRID, 256, SMEM_WORDS * 4>>>(1, b + 128, nullptr, 1, 1, 0);
    // Layer 2: fp32 -> out (no relu); cleanup zeroes deg for next call
    agg_kernel<<<AGRID, 256>>>();
    mma_gemm_kernel<<<PGRID, 256, SMEM_WORDS * 4>>>(2, b + 256, out, 0, 0, 1);
}